// round 1
// baseline (speedup 1.0000x reference)
#include <cuda_runtime.h>
#include <cstdint>
#include <cstddef>

#define T_STEPS 1024
#define BATCH   8
#define DIM     1024
#define NSLOTS  8
#define RANK    256
#define GROUP   16            // CTAs per slot group
#define NCTAS   (NSLOTS*GROUP)

// padded SMEM row strides (floats) — multiples of 4 for float4, +4 for bank spread
#define SV_STRIDE  1028
#define SH_STRIDE  1028
#define SU_STRIDE  260
#define SVH_STRIDE 260

#define SV_ELEMS   (16*SV_STRIDE)    // 16448
#define SU_ELEMS   (64*SU_STRIDE)    // 16640
#define SH_ELEMS   (8*SH_STRIDE)     // 8224
#define SVH_ELEMS  (8*SVH_STRIDE)    // 2080
#define SRED_ELEMS 2048
#define SMEM_FLOATS (SV_ELEMS+SU_ELEMS+SH_ELEMS+SVH_ELEMS+SRED_ELEMS)
#define SMEM_BYTES  (SMEM_FLOATS*4)  // 181760 B < 227KB

// ---------------- device scratch (static, allocation-rule-safe) ----------------
__device__ float    g_wx[(size_t)T_STEPS*BATCH*DIM]; // Wx + bias, [t][b][d]
__device__ float    g_vh[NSLOTS*BATCH*RANK];         // Vh staging, [s][b][r]
__device__ unsigned g_bar[NSLOTS];                   // per-slot monotonic barrier

// packed fp32x2 FMA (full-rate fp32 on sm_103a; 3-reg FFMA is half rate)
__device__ __forceinline__ float2 ffma2(float2 a, float2 b, float2 c) {
    float2 d;
    asm("fma.rn.f32x2 %0, %1, %2, %3;"
        : "=l"(*reinterpret_cast<unsigned long long*>(&d))
        : "l"(*reinterpret_cast<const unsigned long long*>(&a)),
          "l"(*reinterpret_cast<const unsigned long long*>(&b)),
          "l"(*reinterpret_cast<const unsigned long long*>(&c)));
    return d;
}

// ======================= kernel 1: Wx = x @ W^T + bias =======================
// M=8192 (t*B+b), N=1024, K=1024. 64x64 tiles, BK=32, 256 threads, 4x4/thread.
__global__ __launch_bounds__(256) void wx_kernel(const float* __restrict__ x,
                                                 const float* __restrict__ W,
                                                 const float* __restrict__ bias) {
    __shared__ float sA[64*36];
    __shared__ float sB[64*36];
    const int tid = threadIdx.x;
    const int m0 = blockIdx.y * 64;
    const int n0 = blockIdx.x * 64;
    if (blockIdx.x == 0 && blockIdx.y == 0 && tid < NSLOTS) g_bar[tid] = 0u;

    const int tm = tid >> 4;    // 0..15, m in {tm, tm+16, tm+32, tm+48}
    const int tn = tid & 15;    // 0..15, n in {tn, tn+16, tn+32, tn+48}

    float2 acc[4][4];
    #pragma unroll
    for (int i = 0; i < 4; i++)
        #pragma unroll
        for (int j = 0; j < 4; j++) acc[i][j] = make_float2(0.f, 0.f);

    for (int kb = 0; kb < 1024; kb += 32) {
        __syncthreads();
        #pragma unroll
        for (int it = 0; it < 2; it++) {
            int i = tid + it*256;             // 0..511
            int row = i >> 3, c4 = (i & 7) * 4;
            *(float4*)&sA[row*36 + c4] = *(const float4*)&x[(size_t)(m0+row)*1024 + kb + c4];
            *(float4*)&sB[row*36 + c4] = *(const float4*)&W[(size_t)(n0+row)*1024 + kb + c4];
        }
        __syncthreads();
        #pragma unroll
        for (int kk = 0; kk < 32; kk += 2) {
            float2 a[4], b[4];
            #pragma unroll
            for (int i = 0; i < 4; i++) a[i] = *(float2*)&sA[(tm+16*i)*36 + kk];
            #pragma unroll
            for (int j = 0; j < 4; j++) b[j] = *(float2*)&sB[(tn+16*j)*36 + kk];
            #pragma unroll
            for (int i = 0; i < 4; i++)
                #pragma unroll
                for (int j = 0; j < 4; j++)
                    acc[i][j] = ffma2(a[i], b[j], acc[i][j]);
        }
    }
    #pragma unroll
    for (int i = 0; i < 4; i++) {
        int m = m0 + tm + 16*i;
        #pragma unroll
        for (int j = 0; j < 4; j++) {
            int n = n0 + tn + 16*j;
            g_wx[(size_t)m*1024 + n] = acc[i][j].x + acc[i][j].y + bias[n];
        }
    }
}

// ================== kernel 2: persistent recurrence ==================
// grid = 128 CTAs (8 slots x 16 ranks), 256 threads, 1 CTA/SM, all co-resident.
__global__ void __launch_bounds__(256, 1)
recur_kernel(const float* __restrict__ h0, const float* __restrict__ U,
             const float* __restrict__ V, float* __restrict__ hout) {
    extern __shared__ float sm[];
    float* sV   = sm;                    // [16][SV_STRIDE]  V[s][rlo+ri][d]
    float* sU   = sV  + SV_ELEMS;        // [64][SU_STRIDE]  U[s][dlo+di][r]
    float* shT  = sU  + SU_ELEMS;        // [8][SH_STRIDE]   h[t][s][b][d]
    float* sVhT = shT + SH_ELEMS;        // [8][SVH_STRIDE]  Vh[b][r]
    float* sRed = sVhT + SVH_ELEMS;      // 2048 floats scratch

    const int tid = threadIdx.x;
    const int s   = blockIdx.x >> 4;
    const int rk  = blockIdx.x & 15;
    const int rlo = rk * 16;
    const int dlo = rk * 64;

    // load resident weights: V rows [rlo, rlo+16), U rows [dlo, dlo+64)
    for (int i = tid; i < 4096; i += 256) {
        int row = i >> 8, c4 = (i & 255) * 4;
        *(float4*)&sV[row*SV_STRIDE + c4] =
            *(const float4*)&V[((size_t)(s*256 + rlo + row))*1024 + c4];
    }
    for (int i = tid; i < 4096; i += 256) {
        int row = i >> 6, c4 = (i & 63) * 4;
        *(float4*)&sU[row*SU_STRIDE + c4] =
            *(const float4*)&U[((size_t)(s*1024 + dlo + row))*256 + c4];
    }
    // h[0][s][b][dlo..dlo+64) = h0[b][s][dlo..]
    for (int i = tid; i < 512; i += 256) {
        int b = i >> 6, d = i & 63;
        hout[(size_t)s*8192 + b*1024 + dlo + d] = h0[(size_t)b*8192 + s*1024 + dlo + d];
    }

    unsigned epoch = 0;
    auto gbar = [&]() {
        epoch++;
        __threadfence();
        __syncthreads();
        if (tid == 0) {
            atomicAdd(&g_bar[s], 1u);
            unsigned target = (unsigned)GROUP * epoch;
            while (*((volatile unsigned*)&g_bar[s]) < target) { }
        }
        __syncthreads();
    };
    gbar();   // h[0] visible to whole slot group

    // GEMM1 mapping: 16 k-slices x (8 r-threads x 2 b-groups), 2r x 4b per thread
    const int ks1 = tid >> 4;
    const int g1  = tid & 15;
    const int rt  = g1 & 7;
    const int b01 = (g1 >> 3) * 4;
    // GEMM2 mapping: 4 k-slices x (16 d-threads x 4 b-groups), 4d x 2b per thread
    const int ks2 = tid >> 6;
    const int g2  = tid & 63;
    const int dt  = g2 & 15;
    const int b02 = (g2 >> 4) * 2;

    for (int t = 0; t < T_STEPS; t++) {
        // stage h[t][s] (32KB) into shT[b][d]
        const float* hsrc = hout + ((size_t)t*8 + s)*8192;
        for (int i = tid; i < 2048; i += 256) {
            int row = i >> 8, c4 = (i & 255) * 4;
            *(float4*)&shT[row*SH_STRIDE + c4] = *(const float4*)&hsrc[row*1024 + c4];
        }
        __syncthreads();

        // ---- GEMM1: Vh[rlo+r][b] = sum_d V[r][d]*h[b][d]  (pairs over d) ----
        {
            float2 acc[2][4];
            #pragma unroll
            for (int i = 0; i < 2; i++)
                #pragma unroll
                for (int j = 0; j < 4; j++) acc[i][j] = make_float2(0.f, 0.f);
            const int dbase = ks1 * 64;
            #pragma unroll 8
            for (int dd = 0; dd < 64; dd += 2) {
                int d = dbase + dd;
                float2 v0 = *(float2*)&sV[rt*SV_STRIDE + d];
                float2 v1 = *(float2*)&sV[(rt+8)*SV_STRIDE + d];
                #pragma unroll
                for (int j = 0; j < 4; j++) {
                    float2 hh = *(float2*)&shT[(b01+j)*SH_STRIDE + d];
                    acc[0][j] = ffma2(v0, hh, acc[0][j]);
                    acc[1][j] = ffma2(v1, hh, acc[1][j]);
                }
            }
            #pragma unroll
            for (int i = 0; i < 2; i++)
                #pragma unroll
                for (int j = 0; j < 4; j++)
                    sRed[(ks1*16 + rt + 8*i)*8 + b01 + j] = acc[i][j].x + acc[i][j].y;
        }
        __syncthreads();
        if (tid < 128) {   // k-split reduction + publish Vh chunk (transposed)
            int r = tid >> 3, bb = tid & 7;
            float v = 0.f;
            #pragma unroll
            for (int k = 0; k < 16; k++) v += sRed[(k*16 + r)*8 + bb];
            g_vh[(s*8 + bb)*256 + rlo + r] = v;
        }
        gbar();   // barrier A: full Vh visible

        // gather full Vh (L2, bypass L1 — staging buffer is reused every step)
        {
            const float4* src = (const float4*)&g_vh[s*2048];
            for (int i = tid; i < 512; i += 256) {
                float4 v = __ldcg(&src[i]);
                int b = i >> 6, c4 = (i & 63) * 4;
                *(float4*)&sVhT[b*SVH_STRIDE + c4] = v;
            }
        }
        __syncthreads();

        // ---- GEMM2: Uh[dlo+d][b] = sum_r U[d][r]*Vh[b][r]  (pairs over r) ----
        {
            float2 acc[4][2];
            #pragma unroll
            for (int i = 0; i < 4; i++) {
                acc[i][0] = make_float2(0.f, 0.f);
                acc[i][1] = make_float2(0.f, 0.f);
            }
            const int rbase = ks2 * 64;
            #pragma unroll 8
            for (int rr = 0; rr < 64; rr += 2) {
                int r = rbase + rr;
                float2 vh0 = *(float2*)&sVhT[b02*SVH_STRIDE + r];
                float2 vh1 = *(float2*)&sVhT[(b02+1)*SVH_STRIDE + r];
                #pragma unroll
                for (int i = 0; i < 4; i++) {
                    float2 u = *(float2*)&sU[(dt+16*i)*SU_STRIDE + r];
                    acc[i][0] = ffma2(u, vh0, acc[i][0]);
                    acc[i][1] = ffma2(u, vh1, acc[i][1]);
                }
            }
            #pragma unroll
            for (int i = 0; i < 4; i++)
                #pragma unroll
                for (int j = 0; j < 2; j++)
                    sRed[(ks2*8 + b02 + j)*64 + dt + 16*i] = acc[i][j].x + acc[i][j].y;
        }
        __syncthreads();

        // finalize: h_new = tanh(Wx + Uh + b), write h[t+1][s][b][dlo..]
        {
            const float* wxrow = g_wx + (size_t)t * 8192;
            float* hdst = hout + ((size_t)(t+1)*8 + s)*8192;
            #pragma unroll
            for (int o = tid; o < 512; o += 256) {
                int b = o >> 6, d = o & 63;
                float uh = 0.f;
                #pragma unroll
                for (int k = 0; k < 4; k++) uh += sRed[(k*8 + b)*64 + d];
                float hn = tanhf(wxrow[b*1024 + dlo + d] + uh);
                hdst[b*1024 + dlo + d] = hn;
            }
        }
        gbar();   // barrier B: h[t+1] visible to whole slot group
    }
}

// ============== kernel 3: out = (sum_s C_s h[t+1,s]) * silu(z) ==============
__global__ __launch_bounds__(256) void out_kernel(const float* __restrict__ z,
                                                  const float* __restrict__ C,
                                                  const float* __restrict__ hout,
                                                  float* __restrict__ out) {
    size_t idx = (size_t)blockIdx.x * 256 + threadIdx.x;   // < T*B*D exactly
    int t   = (int)(idx >> 13);
    int rem = (int)(idx & 8191);
    float zz  = z[idx];
    float sig = 1.f / (1.f + expf(-zz));
    const float* hb = hout + ((size_t)(t+1))*65536 + rem;
    float acc = 0.f;
    #pragma unroll
    for (int s = 0; s < 8; s++) acc += C[s] * hb[(size_t)s*8192];
    out[idx] = acc * zz * sig;
}

// ================================ launch ================================
extern "C" void kernel_launch(void* const* d_in, const int* in_sizes, int n_in,
                              void* d_out, int out_size) {
    (void)in_sizes; (void)n_in; (void)out_size;
    const float* x    = (const float*)d_in[0];
    const float* z    = (const float*)d_in[1];
    const float* h0   = (const float*)d_in[2];
    const float* Wxm  = (const float*)d_in[3];
    const float* U    = (const float*)d_in[4];
    const float* V    = (const float*)d_in[5];
    const float* bias = (const float*)d_in[6];
    const float* C    = (const float*)d_in[7];

    float* out  = (float*)d_out;
    float* hout = out + (size_t)T_STEPS*BATCH*DIM;   // h region: [T+1][S][B][D]

    cudaFuncSetAttribute(recur_kernel, cudaFuncAttributeMaxDynamicSharedMemorySize,
                         SMEM_BYTES);

    dim3 wgrid(16, 128);                 // N-tiles x M-tiles
    wx_kernel<<<wgrid, 256>>>(x, Wxm, bias);
    recur_kernel<<<NCTAS, 256, SMEM_BYTES>>>(h0, U, V, hout);
    out_kernel<<<32768, 256>>>(z, C, hout, out);
}